// round 2
// baseline (speedup 1.0000x reference)
#include <cuda_runtime.h>
#include <cuda_bf16.h>
#include <cstdint>

// ---------------- problem constants ----------------
#define BSZ 2
#define SEQ 2048
#define DIM 1024
#define NST 16
#define TOK (BSZ * SEQ)      // 4096 tokens
#define KBIG 3072            // 3 x 1024 (hi|hi|lo split-K)
#define NPAD 1152            // 1056 cols (dt 1024 + B 16 + C 16) padded to 9*128

// ---------------- scratch (device globals; no allocs allowed) ----------------
__device__ __nv_bfloat16 g_Abig[(size_t)TOK * KBIG];   // [t][k]  24 MB
__device__ __nv_bfloat16 g_Bbig[(size_t)NPAD * KBIG];  // [n][k]  6.75 MB
__device__ float g_xn [(size_t)TOK * DIM];             // layernormed x, [t][d]
__device__ float g_dtT[(size_t)DIM * TOK];             // softplus(dt), [d][t]
__device__ float g_BT [(size_t)NST * TOK];             // B_in^T [n][t]
__device__ float g_CT [(size_t)NST * TOK];             // C_in^T [n][t]

// ---------------- helpers ----------------
__device__ __forceinline__ uint32_t smem_u32(const void* p) {
    uint32_t a;
    asm("{ .reg .u64 t; cvta.to.shared.u64 t, %1; cvt.u32.u64 %0, t; }"
        : "=r"(a) : "l"(p));
    return a;
}
__device__ __forceinline__ void cp_async16(uint32_t s, const void* g) {
    asm volatile("cp.async.cg.shared.global [%0], [%1], 16;"
                 :: "r"(s), "l"(__cvta_generic_to_global(g)) : "memory");
}
__device__ __forceinline__ void cp_commit() {
    asm volatile("cp.async.commit_group;" ::: "memory");
}
template <int N>
__device__ __forceinline__ void cp_wait() {
    asm volatile("cp.async.wait_group %0;" :: "n"(N) : "memory");
}
__device__ __forceinline__ void ldsm_x4(uint32_t& r0, uint32_t& r1,
                                        uint32_t& r2, uint32_t& r3, uint32_t a) {
    asm volatile("ldmatrix.sync.aligned.m8n8.x4.shared.b16 {%0,%1,%2,%3}, [%4];"
                 : "=r"(r0), "=r"(r1), "=r"(r2), "=r"(r3) : "r"(a));
}
__device__ __forceinline__ void mma16816(float* c, const uint32_t* a,
                                         const uint32_t* b) {
    asm volatile(
        "mma.sync.aligned.m16n8k16.row.col.f32.bf16.bf16.f32 "
        "{%0,%1,%2,%3}, {%4,%5,%6,%7}, {%8,%9}, {%0,%1,%2,%3};"
        : "+f"(c[0]), "+f"(c[1]), "+f"(c[2]), "+f"(c[3])
        : "r"(a[0]), "r"(a[1]), "r"(a[2]), "r"(a[3]), "r"(b[0]), "r"(b[1]));
}

// ============================================================
// Kernel 1: LayerNorm + bf16 hi/lo split pack into A' = [hi|hi|lo]
// ============================================================
__global__ void __launch_bounds__(256) ln_kernel(const float* __restrict__ x,
                                                 const float* __restrict__ gamma,
                                                 const float* __restrict__ beta) {
    const int t = blockIdx.x;
    const int tid = threadIdx.x;
    float4 v = ((const float4*)(x + (size_t)t * DIM))[tid];
    float s  = v.x + v.y + v.z + v.w;
    float ss = v.x * v.x + v.y * v.y + v.z * v.z + v.w * v.w;
#pragma unroll
    for (int o = 16; o; o >>= 1) {
        s  += __shfl_xor_sync(0xffffffffu, s,  o);
        ss += __shfl_xor_sync(0xffffffffu, ss, o);
    }
    __shared__ float red[16];
    const int w = tid >> 5, lane = tid & 31;
    if (lane == 0) { red[w] = s; red[8 + w] = ss; }
    __syncthreads();
    if (tid == 0) {
        float a = 0.f, b2 = 0.f;
#pragma unroll
        for (int i = 0; i < 8; ++i) { a += red[i]; b2 += red[8 + i]; }
        red[0] = a; red[8] = b2;
    }
    __syncthreads();
    const float mu  = red[0] * (1.f / DIM);
    const float var = red[8] * (1.f / DIM) - mu * mu;
    const float rs  = rsqrtf(var + 1e-5f);
    float4 g  = ((const float4*)gamma)[tid];
    float4 bb = ((const float4*)beta)[tid];
    float4 xn;
    xn.x = (v.x - mu) * rs * g.x + bb.x;
    xn.y = (v.y - mu) * rs * g.y + bb.y;
    xn.z = (v.z - mu) * rs * g.z + bb.z;
    xn.w = (v.w - mu) * rs * g.w + bb.w;
    ((float4*)(g_xn + (size_t)t * DIM))[tid] = xn;

    __nv_bfloat16 h0 = __float2bfloat16(xn.x);
    __nv_bfloat16 h1 = __float2bfloat16(xn.y);
    __nv_bfloat16 h2 = __float2bfloat16(xn.z);
    __nv_bfloat16 h3 = __float2bfloat16(xn.w);
    __nv_bfloat16 l0 = __float2bfloat16(xn.x - __bfloat162float(h0));
    __nv_bfloat16 l1 = __float2bfloat16(xn.y - __bfloat162float(h1));
    __nv_bfloat16 l2 = __float2bfloat16(xn.z - __bfloat162float(h2));
    __nv_bfloat16 l3 = __float2bfloat16(xn.w - __bfloat162float(h3));

    __nv_bfloat16* base = g_Abig + (size_t)t * KBIG + tid * 4;
    __nv_bfloat162 hA = __halves2bfloat162(h0, h1);
    __nv_bfloat162 hB = __halves2bfloat162(h2, h3);
    __nv_bfloat162 lA = __halves2bfloat162(l0, l1);
    __nv_bfloat162 lB = __halves2bfloat162(l2, l3);
    ((__nv_bfloat162*)(base))[0]        = hA;
    ((__nv_bfloat162*)(base))[1]        = hB;
    ((__nv_bfloat162*)(base + 1024))[0] = hA;
    ((__nv_bfloat162*)(base + 1024))[1] = hB;
    ((__nv_bfloat162*)(base + 2048))[0] = lA;
    ((__nv_bfloat162*)(base + 2048))[1] = lB;
}

// ============================================================
// Kernel 2: pack weights B' = [hi | lo | hi]
// ============================================================
__global__ void __launch_bounds__(256) wpack_kernel(const float* __restrict__ W_dt,
                                                    const float* __restrict__ W_B,
                                                    const float* __restrict__ W_C) {
    const int r = blockIdx.x;
    const float* wrow = nullptr;
    if (r < 1024)       wrow = W_dt + (size_t)r * DIM;
    else if (r < 1040)  wrow = W_B  + (size_t)(r - 1024) * DIM;
    else if (r < 1056)  wrow = W_C  + (size_t)(r - 1040) * DIM;
    for (int k = threadIdx.x; k < KBIG; k += 256) {
        float wv = 0.f;
        const int kk  = k & 1023;
        const int blk = k >> 10;
        if (wrow) wv = wrow[kk];
        __nv_bfloat16 hi = __float2bfloat16(wv);
        __nv_bfloat16 outv = (blk == 1)
            ? __float2bfloat16(wv - __bfloat162float(hi)) : hi;
        g_Bbig[(size_t)r * KBIG + k] = outv;
    }
}

// ============================================================
// Kernel 3: bf16 mma.sync GEMM, CTA tile 128x128, K=3072 step 32
// A [t][k] row-major (K-major), B [n][k] row-major ("col" operand).
// Epilogue: softplus(dt)+transpose -> g_dtT; B_in/C_in -> g_BT/g_CT.
// ============================================================
#define BK 32
#define SROW 40          // padded smem row stride in bf16 elems (80 B)
#define TILE_ELEMS (128 * SROW)

__global__ void __launch_bounds__(256) gemm_kernel(const float* __restrict__ b_dt) {
    __shared__ __nv_bfloat16 sm[2][2][TILE_ELEMS];   // [buf][A/B][...]

    const int tid  = threadIdx.x;
    const int wid  = tid >> 5;
    const int lane = tid & 31;
    const int mt = blockIdx.x;    // 0..31
    const int nt = blockIdx.y;    // 0..8
    const int warp_m = wid & 3;   // 4 warps along M (32 rows each)
    const int warp_n = wid >> 2;  // 2 warps along N (64 cols each)
    const int m0 = warp_m * 32;
    const int n0 = warp_n * 64;

    const __nv_bfloat16* Ag = g_Abig + (size_t)mt * 128 * KBIG;
    const __nv_bfloat16* Bg = g_Bbig + (size_t)nt * 128 * KBIG;

    const uint32_t sA[2] = { smem_u32(&sm[0][0][0]), smem_u32(&sm[1][0][0]) };
    const uint32_t sB[2] = { smem_u32(&sm[0][1][0]), smem_u32(&sm[1][1][0]) };

    // each thread copies 2 x 16B chunks of A and of B per tile
    const int id0  = tid * 2;
    auto load_tile = [&](int c, int buf) {
        const int k0 = c * BK;
#pragma unroll
        for (int r = 0; r < 2; ++r) {
            const int id  = id0 + r;           // 0..511
            const int row = id >> 2;
            const int ch  = id & 3;
            const uint32_t soff = (uint32_t)(row * SROW + ch * 8) * 2;
            cp_async16(sA[buf] + soff, Ag + (size_t)row * KBIG + k0 + ch * 8);
            cp_async16(sB[buf] + soff, Bg + (size_t)row * KBIG + k0 + ch * 8);
        }
        cp_commit();
    };

    float acc[2][8][4];
#pragma unroll
    for (int mf = 0; mf < 2; ++mf)
#pragma unroll
        for (int nf = 0; nf < 8; ++nf)
#pragma unroll
            for (int i = 0; i < 4; ++i) acc[mf][nf][i] = 0.f;

    const int KITER = KBIG / BK;   // 96
    load_tile(0, 0);

    for (int c = 0; c < KITER; ++c) {
        const int buf = c & 1;
        if (c + 1 < KITER) { load_tile(c + 1, buf ^ 1); cp_wait<1>(); }
        else               { cp_wait<0>(); }
        __syncthreads();

#pragma unroll
        for (int kk = 0; kk < BK; kk += 16) {
            uint32_t a[2][4];
#pragma unroll
            for (int mf = 0; mf < 2; ++mf) {
                uint32_t addr = sA[buf] +
                    (uint32_t)((m0 + mf * 16 + (lane & 15)) * SROW +
                               kk + ((lane >> 4) << 3)) * 2;
                ldsm_x4(a[mf][0], a[mf][1], a[mf][2], a[mf][3], addr);
            }
            uint32_t b[8][2];
#pragma unroll
            for (int g = 0; g < 4; ++g) {   // 16 n-cols per group
                const int nrow = n0 + g * 16 + ((lane >> 4) << 3) + (lane & 7);
                const int kcol = kk + (((lane >> 3) & 1) << 3);
                uint32_t addr = sB[buf] + (uint32_t)(nrow * SROW + kcol) * 2;
                uint32_t r0, r1, r2, r3;
                ldsm_x4(r0, r1, r2, r3, addr);
                b[g * 2][0]     = r0; b[g * 2][1]     = r1;
                b[g * 2 + 1][0] = r2; b[g * 2 + 1][1] = r3;
            }
#pragma unroll
            for (int mf = 0; mf < 2; ++mf)
#pragma unroll
                for (int nf = 0; nf < 8; ++nf)
                    mma16816(acc[mf][nf], a[mf], b[nf]);
        }
        __syncthreads();
    }

    // ---------------- epilogue ----------------
    const int trow = lane >> 2;       // 0..7
    const int cpair = (lane & 3) * 2; // 0,2,4,6
#pragma unroll
    for (int mf = 0; mf < 2; ++mf) {
#pragma unroll
        for (int nf = 0; nf < 8; ++nf) {
            const int token = mt * 128 + m0 + mf * 16 + trow;
            const int dcol  = nt * 128 + n0 + nf * 8 + cpair;
            const float* a4 = acc[mf][nf];
#pragma unroll
            for (int i = 0; i < 4; ++i) {
                const int tt = token + ((i >> 1) << 3);   // +8 for regs 2,3
                const int dd = dcol + (i & 1);
                float v = a4[i];
                if (nt < 8) {
                    v += b_dt[dd];
                    float sp = (v > 20.f) ? v : log1pf(expf(v));
                    g_dtT[(size_t)dd * TOK + tt] = sp;
                } else {
                    const int idx = dd - 1024;
                    if (idx < 16)       g_BT[(size_t)idx * TOK + tt] = v;
                    else if (idx < 32)  g_CT[(size_t)(idx - 16) * TOK + tt] = v;
                }
            }
        }
    }
}

// ============================================================
// Kernel 4: selective scan
// ============================================================
__global__ void __launch_bounds__(256, 1) scan_kernel(const float* __restrict__ x,
                                                      const float* __restrict__ A_log,
                                                      const float* __restrict__ Dp,
                                                      float* __restrict__ out) {
    const int blk = blockIdx.x;          // 0..127
    const int b   = blk >> 6;
    const int d0  = (blk & 63) << 4;
    const int tid = threadIdx.x;
    const int w   = tid >> 5;
    const int lane = tid & 31;
    const int half = lane >> 4;
    const int n    = lane & 15;
    const int d    = d0 + 2 * w + half;

    const float a_coef = -expf(A_log[d * NST + n]) * 1.44269504088896341f;
    const float dpar   = Dp[d];

    const float* dt_row = g_dtT + (size_t)d * TOK + b * SEQ;
    const float* B_row  = g_BT  + (size_t)n * TOK + b * SEQ;
    const float* C_row  = g_CT  + (size_t)n * TOK + b * SEQ;
    const float* xn_p   = g_xn + ((size_t)b * SEQ) * DIM + d;
    const float* x_p    = x    + ((size_t)b * SEQ) * DIM + d;
    float*       out_p  = out  + ((size_t)b * SEQ) * DIM + d;

    float h = 0.f;
    for (int l = 0; l < SEQ; l += 4) {
        const float4 dt4 = *(const float4*)(dt_row + l);
        const float4 B4  = *(const float4*)(B_row  + l);
        const float4 C4  = *(const float4*)(C_row  + l);
        float xns[4], xvs[4];
#pragma unroll
        for (int j = 0; j < 4; ++j) {
            xns[j] = xn_p[(size_t)(l + j) * DIM];
            xvs[j] = x_p[(size_t)(l + j) * DIM];
        }
#pragma unroll
        for (int j = 0; j < 4; ++j) {
            const float dtv = (&dt4.x)[j];
            const float Bv  = (&B4.x)[j];
            const float Cv  = (&C4.x)[j];
            const float a   = exp2f(dtv * a_coef);
            h = fmaf(a, h, dtv * Bv * xns[j]);
            float p = Cv * h;
            p += __shfl_xor_sync(0xffffffffu, p, 8);
            p += __shfl_xor_sync(0xffffffffu, p, 4);
            p += __shfl_xor_sync(0xffffffffu, p, 2);
            p += __shfl_xor_sync(0xffffffffu, p, 1);
            if (n == 0) out_p[(size_t)(l + j) * DIM] = fmaf(dpar, xvs[j], p);
        }
    }
}

// ============================================================
// launch
// ============================================================
extern "C" void kernel_launch(void* const* d_in, const int* in_sizes, int n_in,
                              void* d_out, int out_size) {
    const float* x     = (const float*)d_in[0];
    const float* W_dt  = (const float*)d_in[1];
    const float* b_dt  = (const float*)d_in[2];
    const float* W_B   = (const float*)d_in[3];
    const float* W_C   = (const float*)d_in[4];
    const float* Dp    = (const float*)d_in[5];
    const float* A_log = (const float*)d_in[6];
    const float* gamma = (const float*)d_in[7];
    const float* beta  = (const float*)d_in[8];
    float* out = (float*)d_out;

    ln_kernel<<<TOK, 256>>>(x, gamma, beta);
    wpack_kernel<<<NPAD, 256>>>(W_dt, W_B, W_C);
    dim3 gg(TOK / 128, NPAD / 128);  // 32 x 9
    gemm_kernel<<<gg, 256>>>(b_dt);
    scan_kernel<<<128, 256>>>(x, A_log, Dp, out);
}

// round 3
// speedup vs baseline: 1.5658x; 1.5658x over previous
#include <cuda_runtime.h>
#include <cuda_bf16.h>
#include <cstdint>

// ---------------- problem constants ----------------
#define BSZ 2
#define SEQ 2048
#define DIM 1024
#define NST 16
#define TOK (BSZ * SEQ)      // 4096 tokens
#define KBIG 3072            // 3 x 1024 (hi|hi|lo split-K)
#define NPAD 1152            // 1056 cols (dt 1024 + B 16 + C 16) padded to 9*128

// ---------------- scratch (device globals; no allocs allowed) ----------------
__device__ __nv_bfloat16 g_Abig[(size_t)TOK * KBIG];   // [t][k]  24 MB
__device__ __nv_bfloat16 g_Bbig[(size_t)NPAD * KBIG];  // [n][k]  6.75 MB
__device__ float g_xn [(size_t)TOK * DIM];             // layernormed x, [t][d]
__device__ float g_xnT[(size_t)DIM * TOK];             // xn transposed [d][t]
__device__ float g_dtT[(size_t)DIM * TOK];             // softplus(dt), [d][t]
__device__ float g_BT [(size_t)NST * TOK];             // B_in^T [n][t]
__device__ float g_CT [(size_t)NST * TOK];             // C_in^T [n][t]
__device__ float g_yT [(size_t)DIM * TOK];             // scan output [d][t]

// ---------------- helpers ----------------
__device__ __forceinline__ uint32_t smem_u32(const void* p) {
    uint32_t a;
    asm("{ .reg .u64 t; cvta.to.shared.u64 t, %1; cvt.u32.u64 %0, t; }"
        : "=r"(a) : "l"(p));
    return a;
}
__device__ __forceinline__ void cp_async16(uint32_t s, const void* g) {
    asm volatile("cp.async.cg.shared.global [%0], [%1], 16;"
                 :: "r"(s), "l"(__cvta_generic_to_global(g)) : "memory");
}
__device__ __forceinline__ void cp_commit() {
    asm volatile("cp.async.commit_group;" ::: "memory");
}
template <int N>
__device__ __forceinline__ void cp_wait() {
    asm volatile("cp.async.wait_group %0;" :: "n"(N) : "memory");
}
__device__ __forceinline__ void ldsm_x4(uint32_t& r0, uint32_t& r1,
                                        uint32_t& r2, uint32_t& r3, uint32_t a) {
    asm volatile("ldmatrix.sync.aligned.m8n8.x4.shared.b16 {%0,%1,%2,%3}, [%4];"
                 : "=r"(r0), "=r"(r1), "=r"(r2), "=r"(r3) : "r"(a));
}
__device__ __forceinline__ void mma16816(float* c, const uint32_t* a,
                                         const uint32_t* b) {
    asm volatile(
        "mma.sync.aligned.m16n8k16.row.col.f32.bf16.bf16.f32 "
        "{%0,%1,%2,%3}, {%4,%5,%6,%7}, {%8,%9}, {%0,%1,%2,%3};"
        : "+f"(c[0]), "+f"(c[1]), "+f"(c[2]), "+f"(c[3])
        : "r"(a[0]), "r"(a[1]), "r"(a[2]), "r"(a[3]), "r"(b[0]), "r"(b[1]));
}

// ============================================================
// Kernel 1: LayerNorm + bf16 hi/lo split pack into A' = [hi|hi|lo]
// ============================================================
__global__ void __launch_bounds__(256) ln_kernel(const float* __restrict__ x,
                                                 const float* __restrict__ gamma,
                                                 const float* __restrict__ beta) {
    const int t = blockIdx.x;
    const int tid = threadIdx.x;
    float4 v = ((const float4*)(x + (size_t)t * DIM))[tid];
    float s  = v.x + v.y + v.z + v.w;
    float ss = v.x * v.x + v.y * v.y + v.z * v.z + v.w * v.w;
#pragma unroll
    for (int o = 16; o; o >>= 1) {
        s  += __shfl_xor_sync(0xffffffffu, s,  o);
        ss += __shfl_xor_sync(0xffffffffu, ss, o);
    }
    __shared__ float red[16];
    const int w = tid >> 5, lane = tid & 31;
    if (lane == 0) { red[w] = s; red[8 + w] = ss; }
    __syncthreads();
    if (tid == 0) {
        float a = 0.f, b2 = 0.f;
#pragma unroll
        for (int i = 0; i < 8; ++i) { a += red[i]; b2 += red[8 + i]; }
        red[0] = a; red[8] = b2;
    }
    __syncthreads();
    const float mu  = red[0] * (1.f / DIM);
    const float var = red[8] * (1.f / DIM) - mu * mu;
    const float rs  = rsqrtf(var + 1e-5f);
    float4 g  = ((const float4*)gamma)[tid];
    float4 bb = ((const float4*)beta)[tid];
    float4 xn;
    xn.x = (v.x - mu) * rs * g.x + bb.x;
    xn.y = (v.y - mu) * rs * g.y + bb.y;
    xn.z = (v.z - mu) * rs * g.z + bb.z;
    xn.w = (v.w - mu) * rs * g.w + bb.w;
    ((float4*)(g_xn + (size_t)t * DIM))[tid] = xn;

    __nv_bfloat16 h0 = __float2bfloat16(xn.x);
    __nv_bfloat16 h1 = __float2bfloat16(xn.y);
    __nv_bfloat16 h2 = __float2bfloat16(xn.z);
    __nv_bfloat16 h3 = __float2bfloat16(xn.w);
    __nv_bfloat16 l0 = __float2bfloat16(xn.x - __bfloat162float(h0));
    __nv_bfloat16 l1 = __float2bfloat16(xn.y - __bfloat162float(h1));
    __nv_bfloat16 l2 = __float2bfloat16(xn.z - __bfloat162float(h2));
    __nv_bfloat16 l3 = __float2bfloat16(xn.w - __bfloat162float(h3));

    __nv_bfloat16* base = g_Abig + (size_t)t * KBIG + tid * 4;
    __nv_bfloat162 hA = __halves2bfloat162(h0, h1);
    __nv_bfloat162 hB = __halves2bfloat162(h2, h3);
    __nv_bfloat162 lA = __halves2bfloat162(l0, l1);
    __nv_bfloat162 lB = __halves2bfloat162(l2, l3);
    ((__nv_bfloat162*)(base))[0]        = hA;
    ((__nv_bfloat162*)(base))[1]        = hB;
    ((__nv_bfloat162*)(base + 1024))[0] = hA;
    ((__nv_bfloat162*)(base + 1024))[1] = hB;
    ((__nv_bfloat162*)(base + 2048))[0] = lA;
    ((__nv_bfloat162*)(base + 2048))[1] = lB;
}

// ============================================================
// Kernel 2: pack weights B' = [hi | lo | hi]
// ============================================================
__global__ void __launch_bounds__(256) wpack_kernel(const float* __restrict__ W_dt,
                                                    const float* __restrict__ W_B,
                                                    const float* __restrict__ W_C) {
    const int r = blockIdx.x;
    const float* wrow = nullptr;
    if (r < 1024)       wrow = W_dt + (size_t)r * DIM;
    else if (r < 1040)  wrow = W_B  + (size_t)(r - 1024) * DIM;
    else if (r < 1056)  wrow = W_C  + (size_t)(r - 1040) * DIM;
    for (int k = threadIdx.x; k < KBIG; k += 256) {
        float wv = 0.f;
        const int kk  = k & 1023;
        const int blk = k >> 10;
        if (wrow) wv = wrow[kk];
        __nv_bfloat16 hi = __float2bfloat16(wv);
        __nv_bfloat16 outv = (blk == 1)
            ? __float2bfloat16(wv - __bfloat162float(hi)) : hi;
        g_Bbig[(size_t)r * KBIG + k] = outv;
    }
}

// ============================================================
// Kernel 2b: xn transpose  [t][d] -> [d][t]
// ============================================================
__global__ void __launch_bounds__(256) xpose_kernel() {
    __shared__ float s[32][33];
    const int t0 = blockIdx.x * 32;
    const int d0 = blockIdx.y * 32;
    const int tx = threadIdx.x & 31;
    const int ty = threadIdx.x >> 5;   // 0..7
#pragma unroll
    for (int i = 0; i < 4; ++i)
        s[ty + i * 8][tx] = g_xn[(size_t)(t0 + ty + i * 8) * DIM + d0 + tx];
    __syncthreads();
#pragma unroll
    for (int i = 0; i < 4; ++i)
        g_xnT[(size_t)(d0 + ty + i * 8) * TOK + t0 + tx] = s[tx][ty + i * 8];
}

// ============================================================
// Kernel 3: bf16 mma.sync GEMM, CTA tile 128x128, K=3072 step 32
// Epilogue: smem transpose -> coalesced dtT/BT/CT stores.
// ============================================================
#define BK 32
#define SROW 40          // padded smem row stride in bf16 elems (80 B)
#define TILE_ELEMS (128 * SROW)
#define GEMM_SMEM 40960  // max(pipeline 40960, transpose 64*132*4=33792)

__global__ void __launch_bounds__(256) gemm_kernel(const float* __restrict__ b_dt) {
    extern __shared__ char smem_raw[];

    const int tid  = threadIdx.x;
    const int wid  = tid >> 5;
    const int lane = tid & 31;
    const int mt = blockIdx.x;    // 0..31
    const int nt = blockIdx.y;    // 0..8
    const int warp_m = wid & 3;
    const int warp_n = wid >> 2;
    const int m0 = warp_m * 32;
    const int n0 = warp_n * 64;

    const __nv_bfloat16* Ag = g_Abig + (size_t)mt * 128 * KBIG;
    const __nv_bfloat16* Bg = g_Bbig + (size_t)nt * 128 * KBIG;

    const uint32_t sbase = smem_u32(smem_raw);
    const uint32_t sA[2] = { sbase, sbase + 20480u };
    const uint32_t sB[2] = { sbase + 10240u, sbase + 30720u };

    const int id0  = tid * 2;
    auto load_tile = [&](int c, int buf) {
        const int k0 = c * BK;
#pragma unroll
        for (int r = 0; r < 2; ++r) {
            const int id  = id0 + r;           // 0..511
            const int row = id >> 2;
            const int ch  = id & 3;
            const uint32_t soff = (uint32_t)(row * SROW + ch * 8) * 2;
            cp_async16(sA[buf] + soff, Ag + (size_t)row * KBIG + k0 + ch * 8);
            cp_async16(sB[buf] + soff, Bg + (size_t)row * KBIG + k0 + ch * 8);
        }
        cp_commit();
    };

    float acc[2][8][4];
#pragma unroll
    for (int mf = 0; mf < 2; ++mf)
#pragma unroll
        for (int nf = 0; nf < 8; ++nf)
#pragma unroll
            for (int i = 0; i < 4; ++i) acc[mf][nf][i] = 0.f;

    const int KITER = KBIG / BK;   // 96
    load_tile(0, 0);

    for (int c = 0; c < KITER; ++c) {
        const int buf = c & 1;
        if (c + 1 < KITER) { load_tile(c + 1, buf ^ 1); cp_wait<1>(); }
        else               { cp_wait<0>(); }
        __syncthreads();

#pragma unroll
        for (int kk = 0; kk < BK; kk += 16) {
            uint32_t a[2][4];
#pragma unroll
            for (int mf = 0; mf < 2; ++mf) {
                uint32_t addr = sA[buf] +
                    (uint32_t)((m0 + mf * 16 + (lane & 15)) * SROW +
                               kk + ((lane >> 4) << 3)) * 2;
                ldsm_x4(a[mf][0], a[mf][1], a[mf][2], a[mf][3], addr);
            }
            uint32_t b[8][2];
#pragma unroll
            for (int g = 0; g < 4; ++g) {
                const int nrow = n0 + g * 16 + ((lane >> 4) << 3) + (lane & 7);
                const int kcol = kk + (((lane >> 3) & 1) << 3);
                uint32_t addr = sB[buf] + (uint32_t)(nrow * SROW + kcol) * 2;
                uint32_t r0, r1, r2, r3;
                ldsm_x4(r0, r1, r2, r3, addr);
                b[g * 2][0]     = r0; b[g * 2][1]     = r1;
                b[g * 2 + 1][0] = r2; b[g * 2 + 1][1] = r3;
            }
#pragma unroll
            for (int mf = 0; mf < 2; ++mf)
#pragma unroll
                for (int nf = 0; nf < 8; ++nf)
                    mma16816(acc[mf][nf], a[mf], b[nf]);
        }
        __syncthreads();
    }

    // ---------------- epilogue: smem transpose, coalesced stores ----------------
    float* tb = (float*)smem_raw;                 // [64 cols][132 tokens]
    const int trow  = lane >> 2;
    const int cpair = (lane & 3) * 2;
    const int r   = tid >> 2;                     // 0..63 (d-col within half)
    const int seg = tid & 3;

#pragma unroll 1
    for (int h = 0; h < 2; ++h) {
        __syncthreads();
        if (warp_n == h) {
#pragma unroll
            for (int mf = 0; mf < 2; ++mf)
#pragma unroll
                for (int nf = 0; nf < 8; ++nf)
#pragma unroll
                    for (int i = 0; i < 4; ++i) {
                        const int tok_l = m0 + mf * 16 + trow + 8 * (i >> 1);
                        const int col_l = nf * 8 + cpair + (i & 1);
                        tb[col_l * 132 + tok_l] = acc[mf][nf][i];
                    }
        }
        __syncthreads();
        if (nt < 8) {
            const int dd = nt * 128 + h * 64 + r;
            const float bias = b_dt[dd];
            float* dst = g_dtT + (size_t)dd * TOK + mt * 128;
#pragma unroll
            for (int q = 0; q < 8; ++q) {
                const int tl = seg * 32 + q * 4;
                float4 v = *(float4*)&tb[r * 132 + tl];
                float4 o;
                float u;
                u = v.x + bias; o.x = (u > 20.f) ? u : log1pf(expf(u));
                u = v.y + bias; o.y = (u > 20.f) ? u : log1pf(expf(u));
                u = v.z + bias; o.z = (u > 20.f) ? u : log1pf(expf(u));
                u = v.w + bias; o.w = (u > 20.f) ? u : log1pf(expf(u));
                *(float4*)&dst[tl] = o;
            }
        } else {
            const int cc = h * 64 + r;            // col - 1024
            if (cc < 32) {
                float* dst = (cc < 16 ? g_BT + (size_t)cc * TOK
                                      : g_CT + (size_t)(cc - 16) * TOK) + mt * 128;
#pragma unroll
                for (int q = 0; q < 8; ++q) {
                    const int tl = seg * 32 + q * 4;
                    *(float4*)&dst[tl] = *(float4*)&tb[r * 132 + tl];
                }
            }
        }
    }
}

// ============================================================
// Kernel 4: selective scan, 8-step ILP, interleaved butterflies,
// fully coalesced streams, transposed output.
// ============================================================
__global__ void __launch_bounds__(256, 1) scan_kernel(const float* __restrict__ A_log) {
    const int blk = blockIdx.x;          // 0..127
    const int b   = blk >> 6;
    const int d0  = (blk & 63) << 4;
    const int tid = threadIdx.x;
    const int w   = tid >> 5;
    const int lane = tid & 31;
    const int half = lane >> 4;
    const int n    = lane & 15;
    const int d    = d0 + 2 * w + half;

    const float a_coef = -expf(A_log[d * NST + n]) * 1.44269504088896341f;

    const float* dtp = g_dtT + (size_t)d * TOK + b * SEQ;
    const float* xnp = g_xnT + (size_t)d * TOK + b * SEQ;
    const float* Bp  = g_BT  + (size_t)n * TOK + b * SEQ;
    const float* Cp  = g_CT  + (size_t)n * TOK + b * SEQ;
    float*       yp  = g_yT  + (size_t)d * TOK + b * SEQ;

    float4 cdt0 = *(const float4*)(dtp);
    float4 cdt1 = *(const float4*)(dtp + 4);
    float4 cxn0 = *(const float4*)(xnp);
    float4 cxn1 = *(const float4*)(xnp + 4);
    float4 cB0  = *(const float4*)(Bp);
    float4 cB1  = *(const float4*)(Bp + 4);
    float4 cC0  = *(const float4*)(Cp);
    float4 cC1  = *(const float4*)(Cp + 4);

    float h = 0.f;
    const int jsel = lane & 7;

    for (int l = 0; l < SEQ; l += 8) {
        const int ln = (l + 8 < SEQ) ? l + 8 : 0;   // clamped prefetch
        float4 ndt0 = *(const float4*)(dtp + ln);
        float4 ndt1 = *(const float4*)(dtp + ln + 4);
        float4 nxn0 = *(const float4*)(xnp + ln);
        float4 nxn1 = *(const float4*)(xnp + ln + 4);
        float4 nB0  = *(const float4*)(Bp + ln);
        float4 nB1  = *(const float4*)(Bp + ln + 4);
        float4 nC0  = *(const float4*)(Cp + ln);
        float4 nC1  = *(const float4*)(Cp + ln + 4);

        float p0, p1, p2, p3, p4, p5, p6, p7;
#define SSTEP(dtv, Bv, Cv, xv, pj)                          \
        {                                                   \
            const float a_ = exp2f((dtv) * a_coef);         \
            h = fmaf(a_, h, (dtv) * (Bv) * (xv));           \
            pj = (Cv) * h;                                  \
        }
        SSTEP(cdt0.x, cB0.x, cC0.x, cxn0.x, p0)
        SSTEP(cdt0.y, cB0.y, cC0.y, cxn0.y, p1)
        SSTEP(cdt0.z, cB0.z, cC0.z, cxn0.z, p2)
        SSTEP(cdt0.w, cB0.w, cC0.w, cxn0.w, p3)
        SSTEP(cdt1.x, cB1.x, cC1.x, cxn1.x, p4)
        SSTEP(cdt1.y, cB1.y, cC1.y, cxn1.y, p5)
        SSTEP(cdt1.z, cB1.z, cC1.z, cxn1.z, p6)
        SSTEP(cdt1.w, cB1.w, cC1.w, cxn1.w, p7)
#undef SSTEP

#define RED(m)                                              \
        p0 += __shfl_xor_sync(0xffffffffu, p0, m);          \
        p1 += __shfl_xor_sync(0xffffffffu, p1, m);          \
        p2 += __shfl_xor_sync(0xffffffffu, p2, m);          \
        p3 += __shfl_xor_sync(0xffffffffu, p3, m);          \
        p4 += __shfl_xor_sync(0xffffffffu, p4, m);          \
        p5 += __shfl_xor_sync(0xffffffffu, p5, m);          \
        p6 += __shfl_xor_sync(0xffffffffu, p6, m);          \
        p7 += __shfl_xor_sync(0xffffffffu, p7, m);
        RED(1) RED(2) RED(4) RED(8)
#undef RED

        // after full butterfly every lane holds its half's sum; lanes 0-7 of
        // each half store timesteps l..l+7 (coalesced 32B per half)
        float a0 = (jsel & 4) ? p4 : p0;
        float a1 = (jsel & 4) ? p5 : p1;
        float a2 = (jsel & 4) ? p6 : p2;
        float a3 = (jsel & 4) ? p7 : p3;
        float b0 = (jsel & 2) ? a2 : a0;
        float b1 = (jsel & 2) ? a3 : a1;
        float v  = (jsel & 1) ? b1 : b0;
        if (!(lane & 8)) yp[l + jsel] = v;

        cdt0 = ndt0; cdt1 = ndt1; cxn0 = nxn0; cxn1 = nxn1;
        cB0 = nB0; cB1 = nB1; cC0 = nC0; cC1 = nC1;
    }
}

// ============================================================
// Kernel 5: final transpose + residual: out[t][d] = yT[d][t] + Dp[d]*x[t][d]
// ============================================================
__global__ void __launch_bounds__(256) yfinal_kernel(const float* __restrict__ x,
                                                     const float* __restrict__ Dp,
                                                     float* __restrict__ out) {
    __shared__ float s[32][33];
    const int t0 = blockIdx.x * 32;
    const int d0 = blockIdx.y * 32;
    const int tx = threadIdx.x & 31;
    const int ty = threadIdx.x >> 5;   // 0..7
#pragma unroll
    for (int i = 0; i < 4; ++i)
        s[ty + i * 8][tx] = g_yT[(size_t)(d0 + ty + i * 8) * TOK + t0 + tx];
    __syncthreads();
    const float dp = Dp[d0 + tx];
#pragma unroll
    for (int i = 0; i < 4; ++i) {
        const size_t idx = (size_t)(t0 + ty + i * 8) * DIM + d0 + tx;
        out[idx] = fmaf(dp, x[idx], s[tx][ty + i * 8]);
    }
}

// ============================================================
// launch
// ============================================================
extern "C" void kernel_launch(void* const* d_in, const int* in_sizes, int n_in,
                              void* d_out, int out_size) {
    const float* x     = (const float*)d_in[0];
    const float* W_dt  = (const float*)d_in[1];
    const float* b_dt  = (const float*)d_in[2];
    const float* W_B   = (const float*)d_in[3];
    const float* W_C   = (const float*)d_in[4];
    const float* Dp    = (const float*)d_in[5];
    const float* A_log = (const float*)d_in[6];
    const float* gamma = (const float*)d_in[7];
    const float* beta  = (const float*)d_in[8];
    float* out = (float*)d_out;

    ln_kernel<<<TOK, 256>>>(x, gamma, beta);
    wpack_kernel<<<NPAD, 256>>>(W_dt, W_B, W_C);
    xpose_kernel<<<dim3(TOK / 32, DIM / 32), 256>>>();
    dim3 gg(TOK / 128, NPAD / 128);  // 32 x 9
    gemm_kernel<<<gg, 256, GEMM_SMEM>>>(b_dt);
    scan_kernel<<<128, 256>>>(A_log);
    yfinal_kernel<<<dim3(TOK / 32, DIM / 32), 256>>>(x, Dp, out);
}